// round 4
// baseline (speedup 1.0000x reference)
#include <cuda_runtime.h>
#include <cuda_bf16.h>
#include <math.h>

// Problem dims
#define Nn    128
#define Tt    32
#define TCAP  33
#define Dd    400
#define Ww    512
#define Hh    1024
#define Vv    10000
#define Gg    4096   // 4*H

typedef unsigned long long ull;

// ---------------- device scratch (static, allocation-guard compliant) ----------------
__device__ float g_A[Nn * 16 * Hh];              // A_flat [n][l][h], 8 MB
__device__ float g_h[Nn * Hh];                   // current hidden
__device__ float g_c[Nn * Hh];                   // current cell
__device__ float g_attnP[Nn * Gg];               // (attn @ Wattn) for current step, 2 MB
__device__ float g_xw[(size_t)Tt * Nn * Gg];     // precomputed x_t @ Wx, rows t*128+n, 64 MB
__device__ float g_P[(size_t)Nn * 16 * Gg];      // A_flat @ Wattn, rows n*16+l, 32 MB
__device__ float g_zs[2 * Nn * Gg];              // split-K partials of h@Wh, 4 MB
__device__ float g_hn[(size_t)Tt * Nn * Hh];     // all hidden states, rows t*128+n, 16 MB
__device__ float g_scores[(size_t)Tt * Nn * Vv]; // 4096 x 10000 logits, 164 MB
__device__ float g_nll[Tt * Nn];

// ---------------- f32x2 helpers ----------------
__device__ __forceinline__ ull ffma2(ull a, ull b, ull c) {
    ull d;
    asm("fma.rn.f32x2 %0, %1, %2, %3;" : "=l"(d) : "l"(a), "l"(b), "l"(c));
    return d;
}
__device__ __forceinline__ ull pack2(float x, float y) {
    ull r;
    asm("mov.b64 %0, {%1, %2};" : "=l"(r) : "f"(x), "f"(y));
    return r;
}
__device__ __forceinline__ void unpack2(ull v, float& x, float& y) {
    asm("mov.b64 {%0, %1}, %2;" : "=f"(x), "=f"(y) : "l"(v));
}

// ---------------- 1) feature projection: A[n][l][h] = sum_d F[n][d][l]*Wp[d][h] + bp[h] ----------------
__global__ void proj_kernel(const float* __restrict__ features,
                            const float* __restrict__ W_proj,
                            const float* __restrict__ b_proj) {
    __shared__ float Fs[Dd * 16];
    int n  = blockIdx.y;
    int h0 = blockIdx.x * 128;
    int t  = threadIdx.x;

    const float* F = features + (size_t)n * Dd * 16;
    for (int i = t; i < Dd * 16; i += 256) Fs[i] = F[i];
    __syncthreads();

    int h  = h0 + (t & 127);
    int lb = (t >> 7) * 8;
    float acc[8];
    #pragma unroll
    for (int i = 0; i < 8; i++) acc[i] = 0.f;

    for (int d = 0; d < Dd; d++) {
        float w = W_proj[(size_t)d * Hh + h];
        #pragma unroll
        for (int i = 0; i < 8; i++) acc[i] += Fs[d * 16 + lb + i] * w;
    }
    float bp = b_proj[h];
    #pragma unroll
    for (int i = 0; i < 8; i++)
        g_A[(size_t)n * 16 * Hh + (lb + i) * Hh + h] = acc[i] + bp;
}

// ---------------- 2) h0 = mean over l; init h and c ----------------
__global__ void h0_kernel() {
    int idx = blockIdx.x * blockDim.x + threadIdx.x;
    if (idx >= Nn * Hh) return;
    int n = idx >> 10;
    float s = 0.f;
    #pragma unroll
    for (int l = 0; l < 16; l++) s += g_A[(size_t)n * 16 * Hh + l * Hh + (idx & (Hh - 1))];
    s *= (1.0f / 16.0f);
    g_h[idx] = s;
    g_c[idx] = s;
}

// ---------------- generic f32x2 GEMM body: C[M x N] = A[M x K] * B[K x N] ----------------
// Tile 128x64, BK=32, 256 threads, 8x4 micro-tile, k-pair f32x2 lanes, B-prefetch.
// MODE 0: xw   A = embedding gather (K=512),  B=Wx,      C=g_xw
// MODE 1: P    A = g_A   (2048 rows, K=1024), B=Wattn,   C=g_P
// MODE 2: voc  A = g_hn  (4096 rows, K=1024), B=W_vocab, C=g_scores (+bias, col guard)
// MODE 3: hWh  A = g_h   (128 rows),  split-K=2 over K=1024 via 'by', C=g_zs
template<int MODE>
__device__ __forceinline__ void gemm_body(
    int bx, int by,
    const float* __restrict__ Bmat,
    const int*   __restrict__ captions,
    const float* __restrict__ W_embed,
    const float* __restrict__ bias,
    ull (*As2)[129], ull (*Bs2)[66])
{
    constexpr int KLEN = (MODE == 0 || MODE == 3) ? 512 : 1024;
    constexpr int LDB  = (MODE == 2) ? Vv : Gg;
    constexpr int LDC  = (MODE == 2) ? Vv : Gg;

    const int tid = threadIdx.x;
    const int tx  = tid & 15;      // col group: cols tx + 16*j
    const int ty  = tid >> 4;      // row group: rows ty*8 + i
    const int n0  = bx * 64;

    int m0, kbase;
    float* C;
    if (MODE == 3) {
        m0 = 0; kbase = by * 512;
        C = g_zs + (size_t)by * (Nn * Gg);
    } else {
        m0 = by * 128; kbase = 0;
        C = (MODE == 0) ? g_xw : ((MODE == 1) ? g_P : g_scores);
    }

    // A-fill: thread covers rows ar_base + 32p, k columns kc..kc+3
    const int ar_base = tid >> 3;          // 0..31
    const int kc      = (tid & 7) * 4;     // 0..28
    const float* aptr[4];
    #pragma unroll
    for (int p = 0; p < 4; p++) {
        int gr = m0 + ar_base + p * 32;
        const float* rowp;
        if (MODE == 0) {
            int tok = captions[(gr & 127) * TCAP + (gr >> 7)];
            rowp = W_embed + (size_t)tok * Ww;
        } else if (MODE == 1) {
            rowp = g_A + (size_t)gr * Hh;
        } else if (MODE == 2) {
            rowp = g_hn + (size_t)gr * Hh;
        } else {
            rowp = g_h + (size_t)gr * Hh;
        }
        aptr[p] = rowp + kbase + kc;
    }

    // B-fill: thread covers k-pair bk2 (rows 2bk2, 2bk2+1), cols cg4..cg4+3
    const int bk2 = tid >> 4;            // 0..15
    const int cg4 = (tid & 15) * 4;      // 0..60
    const float* bptr = Bmat + (size_t)(kbase + 2 * bk2) * LDB + n0 + cg4;
    bool bcv[4];
    #pragma unroll
    for (int u = 0; u < 4; u++) bcv[u] = (MODE != 2) || (n0 + cg4 + u < Vv);
    const bool bvec = bcv[0] && bcv[1] && bcv[2] && bcv[3];

    // prefetch first B tile rows into registers
    float4 bA, bB;
    {
        if (bvec) {
            bA = *(const float4*)(bptr);
            bB = *(const float4*)(bptr + LDB);
        } else {
            bA.x = bcv[0] ? bptr[0] : 0.f;  bB.x = bcv[0] ? bptr[LDB + 0] : 0.f;
            bA.y = bcv[1] ? bptr[1] : 0.f;  bB.y = bcv[1] ? bptr[LDB + 1] : 0.f;
            bA.z = bcv[2] ? bptr[2] : 0.f;  bB.z = bcv[2] ? bptr[LDB + 2] : 0.f;
            bA.w = bcv[3] ? bptr[3] : 0.f;  bB.w = bcv[3] ? bptr[LDB + 3] : 0.f;
        }
        bptr += (size_t)32 * LDB;
    }

    ull acc[8][4];
    #pragma unroll
    for (int i = 0; i < 8; i++)
        #pragma unroll
        for (int j = 0; j < 4; j++) acc[i][j] = 0ULL;

    for (int k0 = 0; k0 < KLEN; k0 += 32) {
        // ---- A fill (coalesced 16B row loads -> k-pair layout) ----
        #pragma unroll
        for (int p = 0; p < 4; p++) {
            float4 v = *(const float4*)(aptr[p]);
            aptr[p] += 32;
            int r  = ar_base + p * 32;
            int k2 = kc >> 1;
            As2[k2][r]     = pack2(v.x, v.y);
            As2[k2 + 1][r] = pack2(v.z, v.w);
        }
        // ---- B store (from prefetched regs, k-pair interleave) ----
        *(float4*)&Bs2[bk2][cg4]     = make_float4(bA.x, bB.x, bA.y, bB.y);
        *(float4*)&Bs2[bk2][cg4 + 2] = make_float4(bA.z, bB.z, bA.w, bB.w);
        __syncthreads();

        // ---- prefetch next B tile (overlaps with compute below) ----
        if (k0 + 32 < KLEN) {
            if (bvec) {
                bA = *(const float4*)(bptr);
                bB = *(const float4*)(bptr + LDB);
            } else {
                bA.x = bcv[0] ? bptr[0] : 0.f;  bB.x = bcv[0] ? bptr[LDB + 0] : 0.f;
                bA.y = bcv[1] ? bptr[1] : 0.f;  bB.y = bcv[1] ? bptr[LDB + 1] : 0.f;
                bA.z = bcv[2] ? bptr[2] : 0.f;  bB.z = bcv[2] ? bptr[LDB + 2] : 0.f;
                bA.w = bcv[3] ? bptr[3] : 0.f;  bB.w = bcv[3] ? bptr[LDB + 3] : 0.f;
            }
            bptr += (size_t)32 * LDB;
        }

        // ---- inner product over 16 k-pairs ----
        #pragma unroll
        for (int k2 = 0; k2 < 16; k2++) {
            ull a[8], b[4];
            #pragma unroll
            for (int i = 0; i < 8; i++) a[i] = As2[k2][ty * 8 + i];
            #pragma unroll
            for (int j = 0; j < 4; j++) b[j] = Bs2[k2][tx + 16 * j];
            #pragma unroll
            for (int i = 0; i < 8; i++)
                #pragma unroll
                for (int j = 0; j < 4; j++)
                    acc[i][j] = ffma2(a[i], b[j], acc[i][j]);
        }
        __syncthreads();
    }

    // ---- epilogue: fold lanes, bias, store ----
    #pragma unroll
    for (int i = 0; i < 8; i++) {
        int row = m0 + ty * 8 + i;
        float* crow = C + (size_t)row * LDC;
        #pragma unroll
        for (int j = 0; j < 4; j++) {
            int col = n0 + tx + 16 * j;
            if (MODE != 2 || col < Vv) {
                float lo, hi;
                unpack2(acc[i][j], lo, hi);
                float v = lo + hi;
                if (MODE == 2) v += bias[col];
                crow[col] = v;
            }
        }
    }
}

template<int MODE>
__global__ void __launch_bounds__(256, 2) gemm_f32x2(
    const float* __restrict__ Bmat,
    const int*   __restrict__ captions,
    const float* __restrict__ W_embed,
    const float* __restrict__ bias)
{
    __shared__ ull As2[16][129];
    __shared__ ull Bs2[16][66];
    gemm_body<MODE>(blockIdx.x, blockIdx.y, Bmat, captions, W_embed, bias, As2, Bs2);
}

// ---------------- attention body: w = softmax(h.A/sqrt(H)); attnP = sum_l w_l P[n,l,:] ----------------
// 256 threads; ph aliases 4KB of caller smem, scbuf 32 floats.
__device__ __forceinline__ void attn_body(int n, float* ph, float* scbuf) {
    float* sc  = scbuf;
    float* wsm = scbuf + 16;
    int t = threadIdx.x;

    #pragma unroll
    for (int i = 0; i < 4; i++) ph[t + 256 * i] = g_h[(size_t)n * Hh + t + 256 * i];
    __syncthreads();

    int warp = t >> 5, lane = t & 31;
    #pragma unroll
    for (int li = 0; li < 2; li++) {
        int l = warp + 8 * li;
        const float* Arow = g_A + (size_t)n * 16 * Hh + (size_t)l * Hh;
        float s = 0.f;
        for (int h = lane; h < Hh; h += 32) s += ph[h] * Arow[h];
        #pragma unroll
        for (int o = 16; o > 0; o >>= 1) s += __shfl_xor_sync(0xffffffff, s, o);
        if (lane == 0) sc[l] = s;
    }
    __syncthreads();

    if (t < 32) {
        float v = (t < 16) ? sc[t] * 0.03125f : -1e30f;   // 1/sqrt(1024)
        float m = v;
        #pragma unroll
        for (int o = 16; o > 0; o >>= 1) m = fmaxf(m, __shfl_xor_sync(0xffffffff, m, o));
        float e = (t < 16) ? expf(v - m) : 0.f;
        float se = e;
        #pragma unroll
        for (int o = 16; o > 0; o >>= 1) se += __shfl_xor_sync(0xffffffff, se, o);
        if (t < 16) wsm[t] = e / se;
    }
    __syncthreads();

    const float* Pn = g_P + (size_t)n * 16 * Gg;
    float w0 = wsm[0], w1 = wsm[1], w2 = wsm[2], w3 = wsm[3];
    float w4 = wsm[4], w5 = wsm[5], w6 = wsm[6], w7 = wsm[7];
    float w8 = wsm[8], w9 = wsm[9], wa = wsm[10], wb = wsm[11];
    float wc = wsm[12], wd = wsm[13], we = wsm[14], wf = wsm[15];
    for (int c = t; c < Gg; c += 256) {
        float a = w0 * Pn[c]           + w1 * Pn[c + Gg]       + w2 * Pn[c + 2 * Gg]  + w3 * Pn[c + 3 * Gg]
                + w4 * Pn[c + 4 * Gg]  + w5 * Pn[c + 5 * Gg]   + w6 * Pn[c + 6 * Gg]  + w7 * Pn[c + 7 * Gg]
                + w8 * Pn[c + 8 * Gg]  + w9 * Pn[c + 9 * Gg]   + wa * Pn[c + 10 * Gg] + wb * Pn[c + 11 * Gg]
                + wc * Pn[c + 12 * Gg] + wd * Pn[c + 13 * Gg]  + we * Pn[c + 14 * Gg] + wf * Pn[c + 15 * Gg];
        g_attnP[(size_t)n * Gg + c] = a;
    }
}

// ---------------- fused per-step kernel: blocks 0..127 = h@Wh GEMM (split-K=2), 128..255 = attn ----------------
__global__ void __launch_bounds__(256, 2) step_kernel(const float* __restrict__ Wh) {
    __shared__ ull As2[16][129];
    __shared__ ull Bs2[16][66];
    if (blockIdx.x < 128) {
        gemm_body<3>(blockIdx.x & 63, blockIdx.x >> 6, Wh, nullptr, nullptr, nullptr, As2, Bs2);
    } else {
        attn_body(blockIdx.x - 128, (float*)As2, (float*)Bs2);
    }
}

// ---------------- gates: z = z0+z1+xw+attnP+b; LSTM update; store h into hn[t] ----------------
__device__ __forceinline__ float4 f4add5(float4 a, float4 b, float4 c, float4 d, float4 e) {
    return make_float4(a.x + b.x + c.x + d.x + e.x,
                       a.y + b.y + c.y + d.y + e.y,
                       a.z + b.z + c.z + d.z + e.z,
                       a.w + b.w + c.w + d.w + e.w);
}
__device__ __forceinline__ void lstm1(float zi, float zf, float zo, float zg,
                                      float cin, float& cout, float& hout) {
    float si = 1.f / (1.f + expf(-zi));
    float sf = 1.f / (1.f + expf(-zf));
    float so = 1.f / (1.f + expf(-zo));
    float gg = tanhf(zg);
    cout = sf * cin + si * gg;
    hout = so * tanhf(cout);
}

__global__ void gates_kernel(const float* __restrict__ b, int t) {
    int q = blockIdx.x * blockDim.x + threadIdx.x;     // handles 4 h-elements
    if (q >= (Nn * Hh) / 4) return;
    int idx = q * 4;                  // n*H + h
    int n  = idx >> 10;
    int h4 = (idx & (Hh - 1)) >> 2;   // float4 index within gate row

    const float4* z0 = (const float4*)(g_zs + (size_t)n * Gg);
    const float4* z1 = (const float4*)(g_zs + (size_t)(Nn + n) * Gg);
    const float4* xw = (const float4*)(g_xw + ((size_t)t * Nn + n) * Gg);
    const float4* ap = (const float4*)(g_attnP + (size_t)n * Gg);
    const float4* b4 = (const float4*)b;

    float4 zi = f4add5(z0[h4],       z1[h4],       xw[h4],       ap[h4],       b4[h4]);
    float4 zf = f4add5(z0[h4 + 256], z1[h4 + 256], xw[h4 + 256], ap[h4 + 256], b4[h4 + 256]);
    float4 zo = f4add5(z0[h4 + 512], z1[h4 + 512], xw[h4 + 512], ap[h4 + 512], b4[h4 + 512]);
    float4 zg = f4add5(z0[h4 + 768], z1[h4 + 768], xw[h4 + 768], ap[h4 + 768], b4[h4 + 768]);

    float4 cin = ((const float4*)g_c)[q];
    float4 co, ho;
    lstm1(zi.x, zf.x, zo.x, zg.x, cin.x, co.x, ho.x);
    lstm1(zi.y, zf.y, zo.y, zg.y, cin.y, co.y, ho.y);
    lstm1(zi.z, zf.z, zo.z, zg.z, cin.z, co.z, ho.z);
    lstm1(zi.w, zf.w, zo.w, zg.w, cin.w, co.w, ho.w);

    ((float4*)g_c)[q] = co;
    ((float4*)g_h)[q] = ho;
    ((float4*)(g_hn + (size_t)t * Nn * Hh))[q] = ho;
}

// ---------------- per-row log-softmax NLL (masked) ----------------
__global__ void loss_kernel(const int* __restrict__ captions) {
    int r = blockIdx.x;            // r = t*128 + n
    int t = r >> 7, n = r & 127;
    int target = captions[n * TCAP + t + 1];
    const float* s = g_scores + (size_t)r * Vv;
    __shared__ float red[256];
    int tid = threadIdx.x;

    // Vv = 10000 = 2500 float4s
    const float4* s4 = (const float4*)s;
    float m = -1e30f;
    for (int v = tid; v < 2500; v += 256) {
        float4 q = s4[v];
        m = fmaxf(m, fmaxf(fmaxf(q.x, q.y), fmaxf(q.z, q.w)));
    }
    red[tid] = m; __syncthreads();
    for (int o = 128; o > 0; o >>= 1) {
        if (tid < o) red[tid] = fmaxf(red[tid], red[tid + o]);
        __syncthreads();
    }
    float mx = red[0];
    __syncthreads();

    float se = 0.f;
    for (int v = tid; v < 2500; v += 256) {
        float4 q = s4[v];
        se += expf(q.x - mx) + expf(q.y - mx) + expf(q.z - mx) + expf(q.w - mx);
    }
    red[tid] = se; __syncthreads();
    for (int o = 128; o > 0; o >>= 1) {
        if (tid < o) red[tid] += red[tid + o];
        __syncthreads();
    }
    if (tid == 0) {
        float lse = logf(red[0]) + mx;
        float nll = lse - s[target];
        g_nll[r] = (target != 0) ? nll : 0.f;
    }
}

// ---------------- deterministic final reduction ----------------
__global__ void finalize_kernel(float* out) {
    __shared__ float red[256];
    int tid = threadIdx.x;
    float s = 0.f;
    for (int i = tid; i < Tt * Nn; i += 256) s += g_nll[i];
    red[tid] = s; __syncthreads();
    for (int o = 128; o > 0; o >>= 1) {
        if (tid < o) red[tid] += red[tid + o];
        __syncthreads();
    }
    if (tid == 0) out[0] = red[0] * (1.0f / (float)Nn);
}

// ---------------- launch ----------------
extern "C" void kernel_launch(void* const* d_in, const int* in_sizes, int n_in,
                              void* d_out, int out_size) {
    const float* features = (const float*)d_in[0];
    const int*   captions = (const int*)  d_in[1];
    const float* W_embed  = (const float*)d_in[2];
    const float* W_proj   = (const float*)d_in[3];
    const float* b_proj   = (const float*)d_in[4];
    const float* Wx       = (const float*)d_in[5];
    const float* Wh       = (const float*)d_in[6];
    const float* Wattn    = (const float*)d_in[7];
    const float* b        = (const float*)d_in[8];
    const float* W_vocab  = (const float*)d_in[9];
    const float* b_vocab  = (const float*)d_in[10];
    float* out = (float*)d_out;

    proj_kernel<<<dim3(8, 128), 256>>>(features, W_proj, b_proj);
    h0_kernel<<<512, 256>>>();

    // precompute x@Wx for all steps (rows t*128+n) and P = A_flat@Wattn (rows n*16+l)
    gemm_f32x2<0><<<dim3(64, 32), 256>>>(Wx,    captions, W_embed, nullptr);
    gemm_f32x2<1><<<dim3(64, 16), 256>>>(Wattn, captions, W_embed, nullptr);

    for (int t = 0; t < Tt; t++) {
        step_kernel<<<256, 256>>>(Wh);          // attn + h@Wh (split-K=2), concurrent block roles
        gates_kernel<<<128, 256>>>(b, t);
    }

    gemm_f32x2<2><<<dim3(157, 32), 256>>>(W_vocab, captions, W_embed, b_vocab);
    loss_kernel<<<Tt * Nn, 256>>>(captions);
    finalize_kernel<<<1, 256>>>(out);
}